// round 10
// baseline (speedup 1.0000x reference)
#include <cuda_runtime.h>
#include <math.h>
#include <stdint.h>

#define T_DIM   8000
#define F_DIM   80
#define B_DIM   64
#define NROWS   (B_DIM * F_DIM)        // 5120
#define ROW_BYTES 32000                // 8000 * 4
#define NV4     2000                   // float4s per row
#define NTHREADS 512
#define NWARPS  (NTHREADS / 32)
#define DEPTH   3                      // pipeline stages (3 x 32KB smem)
#define NCTAS   304                    // 2 per SM on 152 SMs
#define EPS     1e-10f

__device__ __forceinline__ uint32_t smem_u32(const void* p) {
    return (uint32_t)__cvta_generic_to_shared(p);
}

__device__ __forceinline__ void mbar_init(uint32_t m) {
    asm volatile("mbarrier.init.shared.b64 [%0], 1;" :: "r"(m) : "memory");
}

__device__ __forceinline__ void mbar_wait(uint32_t m, uint32_t parity) {
    asm volatile(
        "{\n\t"
        ".reg .pred P;\n\t"
        "WAIT_%=:\n\t"
        "mbarrier.try_wait.parity.acquire.cta.shared::cta.b64 P, [%0], %1, 0x989680;\n\t"
        "@P bra DONE_%=;\n\t"
        "bra WAIT_%=;\n\t"
        "DONE_%=:\n\t"
        "}"
        :: "r"(m), "r"(parity) : "memory");
}

__device__ __forceinline__ void issue_row_load(uint32_t dst_smem, const float* src,
                                               uint32_t mbar) {
    asm volatile("mbarrier.arrive.expect_tx.shared.b64 _, [%0], %1;"
                 :: "r"(mbar), "r"((uint32_t)ROW_BYTES) : "memory");
    asm volatile("cp.async.bulk.shared::cluster.global.mbarrier::complete_tx::bytes "
                 "[%0], [%1], %2, [%3];"
                 :: "r"(dst_smem), "l"(src), "r"((uint32_t)ROW_BYTES), "r"(mbar)
                 : "memory");
}

__global__ __launch_bounds__(NTHREADS, 2)
void isn_kernel(const float* __restrict__ x,
                const float* __restrict__ lengths,
                float* __restrict__ out)
{
    extern __shared__ float sbuf[];            // DEPTH * 8000 floats
    __shared__ uint64_t mbar[DEPTH];
    __shared__ float sh_s[NWARPS];
    __shared__ float sh_ss[NWARPS];
    __shared__ float sh_mean, sh_rstd;

    const int tid  = threadIdx.x;
    const int bid  = blockIdx.x;
    const int lane = tid & 31;
    const int wid  = tid >> 5;

    // ---- init mbarriers + prologue loads ----
    if (tid == 0) {
        #pragma unroll
        for (int s = 0; s < DEPTH; s++) mbar_init(smem_u32(&mbar[s]));
        asm volatile("fence.proxy.async.shared::cta;" ::: "memory");
    }
    __syncthreads();

    if (tid == 0) {
        #pragma unroll
        for (int s = 0; s < DEPTH; s++) {
            const int row = bid + s * NCTAS;
            if (row < NROWS)
                issue_row_load(smem_u32(&sbuf[s * T_DIM]),
                               x + (size_t)row * T_DIM,
                               smem_u32(&mbar[s]));
        }
    }

    // ---- pipelined main loop ----
    int it = 0;
    for (int row = bid; row < NROWS; row += NCTAS, ++it) {
        const int s   = it % DEPTH;
        const int par = (it / DEPTH) & 1;

        mbar_wait(smem_u32(&mbar[s]), (uint32_t)par);

        const int b = row / F_DIM;
        const int n = (int)rintf(__ldg(&lengths[b]) * (float)T_DIM);

        // smem -> regs + masked accumulate (all smem reads of slot s finish here)
        const float4* __restrict__ buf = reinterpret_cast<const float4*>(&sbuf[s * T_DIM]);
        float4 v[4];
        float sum = 0.0f, ssum = 0.0f;

        #pragma unroll
        for (int k = 0; k < 4; k++) {
            const int idx = tid + k * NTHREADS;
            if (idx < NV4) {
                v[k] = buf[idx];
                const int e = idx * 4;
                if (e + 3 < n) {
                    sum  += v[k].x + v[k].y + v[k].z + v[k].w;
                    ssum += v[k].x * v[k].x + v[k].y * v[k].y
                          + v[k].z * v[k].z + v[k].w * v[k].w;
                } else {
                    float a;
                    a = (e + 0 < n) ? v[k].x : 0.0f; sum += a; ssum += a * a;
                    a = (e + 1 < n) ? v[k].y : 0.0f; sum += a; ssum += a * a;
                    a = (e + 2 < n) ? v[k].z : 0.0f; sum += a; ssum += a * a;
                    a = (e + 3 < n) ? v[k].w : 0.0f; sum += a; ssum += a * a;
                }
            }
        }

        #pragma unroll
        for (int off = 16; off > 0; off >>= 1) {
            sum  += __shfl_down_sync(0xFFFFFFFFu, sum,  off);
            ssum += __shfl_down_sync(0xFFFFFFFFu, ssum, off);
        }
        if (lane == 0) { sh_s[wid] = sum; sh_ss[wid] = ssum; }
        __syncthreads();
        // slot s fully consumed -> refill it immediately (overlaps the reduction tail)
        if (tid == 0) {
            const int nrow = row + DEPTH * NCTAS;
            if (nrow < NROWS)
                issue_row_load(smem_u32(&sbuf[s * T_DIM]),
                               x + (size_t)nrow * T_DIM,
                               smem_u32(&mbar[s]));

            float ts = 0.0f, tss = 0.0f;
            #pragma unroll
            for (int w = 0; w < NWARPS; w++) { ts += sh_s[w]; tss += sh_ss[w]; }
            const float nf   = (float)n;
            const float mean = ts / nf;
            const float var  = (tss - ts * mean) / (nf - 1.0f);
            sh_mean = mean;
            sh_rstd = 1.0f / fmaxf(sqrtf(fmaxf(var, 0.0f)), EPS);
        }
        __syncthreads();

        const float mean = sh_mean;
        const float rstd = sh_rstd;

        float4* __restrict__ orow = reinterpret_cast<float4*>(out + (size_t)row * T_DIM);
        #pragma unroll
        for (int k = 0; k < 4; k++) {
            const int idx = tid + k * NTHREADS;
            if (idx < NV4) {
                float4 o;
                o.x = (v[k].x - mean) * rstd;
                o.y = (v[k].y - mean) * rstd;
                o.z = (v[k].z - mean) * rstd;
                o.w = (v[k].w - mean) * rstd;
                __stcs(&orow[idx], o);
            }
        }
    }
}

extern "C" void kernel_launch(void* const* d_in, const int* in_sizes, int n_in,
                              void* d_out, int out_size)
{
    const float* x       = (const float*)d_in[0];
    const float* lengths = (const float*)d_in[1];
    float*       out     = (float*)d_out;

    const int smem_bytes = DEPTH * ROW_BYTES;  // 96000
    cudaFuncSetAttribute(isn_kernel, cudaFuncAttributeMaxDynamicSharedMemorySize,
                         smem_bytes);
    isn_kernel<<<NCTAS, NTHREADS, smem_bytes>>>(x, lengths, out);
}

// round 13
// speedup vs baseline: 1.1363x; 1.1363x over previous
#include <cuda_runtime.h>
#include <math.h>

#define T_DIM 8000
#define F_DIM 80
#define B_DIM 64
#define NV4   2000          // float4s per row
#define NTHREADS 512
#define V_PER_THREAD 4      // ceil(2000/512)
#define NWARPS (NTHREADS / 32)
#define EPS 1e-10f

__global__ __launch_bounds__(NTHREADS)
void isn_kernel(const float* __restrict__ x,
                const float* __restrict__ lengths,
                float* __restrict__ out)
{
    const int f = blockIdx.x;
    const int b = blockIdx.y;
    const size_t row_off = (size_t)(b * F_DIM + f) * T_DIM;
    const float4* __restrict__ row  = reinterpret_cast<const float4*>(x + row_off);
    float4*       __restrict__ orow = reinterpret_cast<float4*>(out + row_off);

    // n = round(lengths[b] * T), round-half-to-even to match jnp.round
    const int n = (int)rintf(lengths[b] * (float)T_DIM);

    const int tid = threadIdx.x;

    // ---- Pass 1: load row into registers (streaming), masked accumulate ----
    float4 v[V_PER_THREAD];
    float s = 0.0f, ss = 0.0f;

#pragma unroll
    for (int i = 0; i < V_PER_THREAD; i++) {
        const int idx = tid + i * NTHREADS;          // float4 index
        if (idx < NV4) {
            v[i] = __ldcs(&row[idx]);
        }
    }

#pragma unroll
    for (int i = 0; i < V_PER_THREAD; i++) {
        const int idx = tid + i * NTHREADS;
        if (idx < NV4) {
            const int e = idx * 4;                   // element index of .x
            if (e + 3 < n) {
                // fully valid vector — no masking needed
                s  += v[i].x + v[i].y + v[i].z + v[i].w;
                ss += v[i].x * v[i].x + v[i].y * v[i].y
                    + v[i].z * v[i].z + v[i].w * v[i].w;
            } else {
                float a;
                a = (e + 0 < n) ? v[i].x : 0.0f; s += a; ss += a * a;
                a = (e + 1 < n) ? v[i].y : 0.0f; s += a; ss += a * a;
                a = (e + 2 < n) ? v[i].z : 0.0f; s += a; ss += a * a;
                a = (e + 3 < n) ? v[i].w : 0.0f; s += a; ss += a * a;
            }
        }
    }

    // ---- Warp reduction, then ONE barrier; all threads finish redundantly ----
#pragma unroll
    for (int off = 16; off > 0; off >>= 1) {
        s  += __shfl_down_sync(0xFFFFFFFFu, s,  off);
        ss += __shfl_down_sync(0xFFFFFFFFu, ss, off);
    }

    __shared__ float sh_s[NWARPS];
    __shared__ float sh_ss[NWARPS];

    const int lane = tid & 31;
    const int wid  = tid >> 5;
    if (lane == 0) { sh_s[wid] = s; sh_ss[wid] = ss; }
    __syncthreads();

    // Every thread sums the 16 warp partials (broadcast LDS, conflict-free)
    float ts = 0.0f, tss = 0.0f;
#pragma unroll
    for (int w = 0; w < NWARPS; w++) { ts += sh_s[w]; tss += sh_ss[w]; }

    const float nf   = (float)n;
    const float mean = ts / nf;
    const float var  = (tss - ts * mean) / (nf - 1.0f);
    const float rstd = 1.0f / fmaxf(sqrtf(fmaxf(var, 0.0f)), EPS);

    // ---- Pass 2: normalize from registers, streaming vectorized store ----
#pragma unroll
    for (int i = 0; i < V_PER_THREAD; i++) {
        const int idx = tid + i * NTHREADS;
        if (idx < NV4) {
            float4 o;
            o.x = (v[i].x - mean) * rstd;
            o.y = (v[i].y - mean) * rstd;
            o.z = (v[i].z - mean) * rstd;
            o.w = (v[i].w - mean) * rstd;
            __stcs(&orow[idx], o);
        }
    }
}

extern "C" void kernel_launch(void* const* d_in, const int* in_sizes, int n_in,
                              void* d_out, int out_size)
{
    const float* x       = (const float*)d_in[0];
    const float* lengths = (const float*)d_in[1];
    float*       out     = (float*)d_out;

    dim3 grid(F_DIM, B_DIM);
    isn_kernel<<<grid, NTHREADS>>>(x, lengths, out);
}